// round 4
// baseline (speedup 1.0000x reference)
#include <cuda_runtime.h>
#include <cstdint>
#include <cstddef>

#define NB      8
#define NPTS    16384
#define KNB     32
#define CNUM    256
#define CLEN    32
#define PBLK    128

// ----------------- global scratch -----------------
__device__ float  g_flat[(size_t)NB * NPTS * 64];   // point-major gated features
__device__ float  g_xatt[NB * NPTS];
__device__ int    g_start[2048];
__device__ float  g_mmraw[4096];
__device__ double g_part[PBLK][8];
__device__ unsigned int g_barcnt;

// ----------------- K1: gate + transpose -----------------
__global__ void k_prep(const float* __restrict__ x, const float* __restrict__ attw) {
    __shared__ float sx[64][129];
    __shared__ float satt[128];
    __shared__ float swa[64];
    int t = threadIdx.x;                 // 256 threads
    int tile = blockIdx.x;               // 8 * 128
    int b = tile >> 7, p0 = (tile & 127) << 7;

    if (t < 64) swa[t] = attw[t];
    for (int i = t; i < 64 * 128; i += 256) {
        int c = i >> 7, p = i & 127;
        sx[c][p] = x[((size_t)(b * 64 + c) << 14) + p0 + p];
    }
    __syncthreads();
    if (t < 128) {
        float s = 0.f;
#pragma unroll
        for (int c = 0; c < 64; c++) s += sx[c][t] * swa[c];
        float a = 1.f / (1.f + expf(-s));
        satt[t] = a;
        g_xatt[((size_t)b << 14) + p0 + t] = a;
    }
    __syncthreads();
    for (int i = t; i < 128 * 64; i += 256) {
        int p = i >> 6, c = i & 63;
        g_flat[(((size_t)b << 14) + (size_t)(p0 + p)) * 64 + c] = sx[c][p] * satt[p];
    }
    if (tile == 0 && t == 0) g_barcnt = 0u;
}

// ----------------- K2: exact top-256 per batch (bitonic in smem) -----------------
__global__ void __launch_bounds__(1024, 1) k_topk() {
    extern __shared__ unsigned long long keys[];   // 16384 * 8B = 128 KB
    int b = blockIdx.x, t = threadIdx.x;
    for (int i = t; i < NPTS; i += 1024) {
        unsigned int fb = __float_as_uint(g_xatt[((size_t)b << 14) + i]); // positive floats
        keys[i] = ((unsigned long long)fb << 32) | (unsigned int)(0xFFFFFFFFu - (unsigned)i);
    }
    for (int size = 2; size <= NPTS; size <<= 1) {
        for (int stride = size >> 1; stride > 0; stride >>= 1) {
            __syncthreads();
            for (int i = t; i < NPTS / 2; i += 1024) {
                int pos = 2 * i - (i & (stride - 1));
                unsigned long long a = keys[pos], bb = keys[pos + stride];
                bool asc = (pos & size) != 0;                 // overall: descending
                bool sw = asc ? (a > bb) : (a < bb);
                if (sw) { keys[pos] = bb; keys[pos + stride] = a; }
            }
        }
    }
    __syncthreads();
    if (t < CNUM) {
        unsigned low = (unsigned)(keys[t] & 0xFFFFFFFFull);
        int p = (int)(0xFFFFFFFFu - low);
        g_start[(b << 8) + t] = (b << 14) + p;
    }
}

// ----------------- K3: persistent curve walk -----------------
struct SW {
    float  cur[16][64], pre[16][64];
    float4 pk4[16][64];                 // (w1, cur, a, 0) per channel
    float  w1[64], w2[64], mw[256];
    float  lpv[16][32], dotv[16][32], nb2[16][32];
    int    pts[16][32];
    float  hpart[16][3][32];
    float  red[16][2][2];
    float  mm0[16], mm1[16], lpre[16], na[16], ga[16], gb[16];
    float  Ssum[16], SSsum[16];
    int    fcur[16], sel[16];
    float  ag, ab, mg0, mg1, mb0, mb1;
    float  bnf[8];
    double bns[8];
};

__device__ __forceinline__ float wredsum(float v) {
#pragma unroll
    for (int o = 16; o; o >>= 1) v += __shfl_xor_sync(0xffffffffu, v, o);
    return v;
}

__device__ __forceinline__ void grid_bar() {
    __syncthreads();
    if (threadIdx.x == 0) {
        __threadfence();
        unsigned tok = atomicAdd(&g_barcnt, 1u);
        unsigned target = (tok / PBLK + 1u) * PBLK;
        unsigned v;
        do {
            asm volatile("ld.global.acquire.gpu.u32 %0, [%1];" : "=r"(v) : "l"(&g_barcnt));
        } while (v < target);
    }
    __syncthreads();
}

__global__ void __launch_bounds__(1024, 1) k_walk(
    const int* __restrict__ idx,
    const float* __restrict__ agw, const float* __restrict__ agg, const float* __restrict__ agb,
    const float* __restrict__ mwi, const float* __restrict__ mgi, const float* __restrict__ mbi,
    float* __restrict__ out)
{
    __shared__ SW sm;
    extern __shared__ float pv[];   // [16][32][65] = 133120 B
    int t = threadIdx.x;
    int s = t >> 6, t64 = t & 63, half = t64 >> 5, lane = t & 31, c = t64;
    int gi = (blockIdx.x << 4) + s;
    int b = gi >> 8, j = gi & 255, boff = b << 14;

    if (t < 64) { sm.w1[t] = agw[t]; sm.w2[t] = agw[64 + t]; }
    if (t >= 64 && t < 320) sm.mw[t - 64] = mwi[t - 64];
    if (t == 0) {
        sm.ag = agg[0]; sm.ab = agb[0];
        sm.mg0 = mgi[0]; sm.mg1 = mgi[1]; sm.mb0 = mbi[0]; sm.mb1 = mbi[1];
    }
    if (t64 == 0) sm.fcur[s] = g_start[gi];
    __syncthreads();

    for (int step = 0; step < CLEN; step++) {
        // ================= phase A =================
        if (step > 0) {
            float cm = sm.cur[s][c], pm = sm.pre[s][c];
            float r0 = sm.mw[c] * cm + sm.mw[64 + c] * pm;
            float r1 = sm.mw[128 + c] * cm + sm.mw[192 + c] * pm;
            r0 = wredsum(r0); r1 = wredsum(r1);
            if (lane == 0) { sm.red[s][half][0] = r0; sm.red[s][half][1] = r1; }
        }
        if (t64 < 32) sm.pts[s][t64] = idx[(size_t)sm.fcur[s] * KNB + t64] + boff;
        __syncthreads();
        if (step > 0 && t64 == 0) {
            float m0 = sm.red[s][0][0] + sm.red[s][1][0];
            float m1 = sm.red[s][0][1] + sm.red[s][1][1];
            sm.mm0[s] = m0; sm.mm1[s] = m1;
            g_mmraw[2 * gi] = m0; g_mmraw[2 * gi + 1] = m1;
        }
        // gather 32 neighbor rows into shared (coalesced)
        {
            float* dst = &pv[(s * 32) * 65 + c];
#pragma unroll 4
            for (int k = 0; k < KNB; k++) {
                int pt = sm.pts[s][k];
                dst[k * 65] = __ldg(&g_flat[((size_t)pt << 6) + c]);
            }
        }
        __syncthreads();

        if (step > 0) {
            // momentum partials (4 quantities)
            if (t < 64) {
                int q = t >> 4, ss = t & 15;
                float m0 = sm.mm0[ss], m1 = sm.mm1[ss];
                double v = (q == 0) ? (double)m0 : (q == 1) ? (double)m1 :
                           (q == 2) ? (double)m0 * m0 : (double)m1 * m1;
#pragma unroll
                for (int o = 8; o; o >>= 1) v += __shfl_xor_sync(0xffffffffu, v, o, 16);
                if ((t & 15) == 0) g_part[blockIdx.x][q] = v;
            }
            grid_bar();   // -------- bar 1 --------

            // ============== phase B: momentum BN + gates + pre update ==============
            if (t < 128) {
                int w = t >> 5, ll = t & 31;
                double a = g_part[ll][w] + g_part[ll + 32][w]
                         + g_part[ll + 64][w] + g_part[ll + 96][w];
#pragma unroll
                for (int o = 16; o; o >>= 1) a += __shfl_xor_sync(0xffffffffu, a, o);
                if (ll == 0) sm.bns[w] = a;
            }
            __syncthreads();
            if (t == 0) {
                double m0 = sm.bns[0] * (1.0 / 2048.0), m1 = sm.bns[1] * (1.0 / 2048.0);
                double v0 = sm.bns[2] * (1.0 / 2048.0) - m0 * m0;
                double v1 = sm.bns[3] * (1.0 / 2048.0) - m1 * m1;
                sm.bnf[0] = (float)m0; sm.bnf[1] = (float)(1.0 / sqrt(v0 + 1e-5));
                sm.bnf[2] = (float)m1; sm.bnf[3] = (float)(1.0 / sqrt(v1 + 1e-5));
            }
            __syncthreads();
            if (t64 == 0) {
                // torch-.view reshape: curve j reads channel (2j)/256 of curve (2j)%256, etc.
                int p0 = 2 * j, p1 = 2 * j + 1;
                int q0 = p0 & 255, o0 = p0 >> 8, q1 = p1 & 255, o1 = p1 >> 8;
                const float* mr = &g_mmraw[(b << 8) * 2];
                float mean0 = sm.bnf[0], is0 = sm.bnf[1], mean1 = sm.bnf[2], is1 = sm.bnf[3];
                float am0 = mr[2 * q0], am1 = mr[2 * q0 + 1];
                float z0 = (am0 - mean0) * is0 * sm.mg0 + sm.mb0;
                float z1 = (am1 - mean1) * is1 * sm.mg1 + sm.mb1;
                float mx = fmaxf(z0, z1);
                float e0 = expf(z0 - mx), e1 = expf(z1 - mx);
                float gaV = ((o0 == 0) ? e0 : e1) / (e0 + e1);
                float bm0 = mr[2 * q1], bm1 = mr[2 * q1 + 1];
                z0 = (bm0 - mean0) * is0 * sm.mg0 + sm.mb0;
                z1 = (bm1 - mean1) * is1 * sm.mg1 + sm.mb1;
                mx = fmaxf(z0, z1);
                e0 = expf(z0 - mx); e1 = expf(z1 - mx);
                float gbV = ((o1 == 0) ? e0 : e1) / (e0 + e1);
                sm.ga[s] = gaV; sm.gb[s] = gbV;
            }
            __syncthreads();
            {
                float cu = sm.cur[s][c], po = sm.pre[s][c];
                float pnew = sm.ga[s] * cu + sm.gb[s] * po;   // new pre (elementwise, like ref)
                sm.pre[s][c] = pnew;
                float ac = cu - pnew;                          // a = cur - pre_new
                sm.pk4[s][c] = make_float4(sm.w1[c], cu, ac, 0.f);
                float r0 = ac * ac, r1 = sm.w2[c] * pnew;
                r0 = wredsum(r0); r1 = wredsum(r1);
                if (lane == 0) { sm.red[s][half][0] = r0; sm.red[s][half][1] = r1; }
            }
            __syncthreads();
            if (t64 == 0) {
                sm.na[s]   = sqrtf(sm.red[s][0][0] + sm.red[s][1][0]);
                sm.lpre[s] = sm.red[s][0][1] + sm.red[s][1][1];
            }
            __syncthreads();
        } else {
            // step 0: pre = flat[start], lpre = w2 . pre
            int fc = sm.fcur[s];
            float pf = g_flat[((size_t)fc << 6) + c];
            sm.pre[s][c] = pf;
            sm.pk4[s][c] = make_float4(sm.w1[c], 0.f, 0.f, 0.f);
            float r1 = wredsum(sm.w2[c] * pf);
            if (lane == 0) sm.red[s][half][0] = r1;
            __syncthreads();
            if (t64 == 0) sm.lpre[s] = sm.red[s][0][0] + sm.red[s][1][0];
            __syncthreads();
        }

        // ============== per-k reductions: lane = k, each warp does 32 channels ==============
        {
            int off = half * 32;
            const float* pvb = &pv[(s * 32 + lane) * 65 + off];
            const float4* pk = &sm.pk4[s][off];
            float accL = 0.f, accD = 0.f, accN = 0.f;
#pragma unroll 8
            for (int cc = 0; cc < 32; cc++) {
                float v = pvb[cc];
                float4 q = pk[cc];
                accL += v * q.x;
                if (step > 0) {
                    float nb = v - q.y;
                    accD += q.z * nb;
                    accN += nb * nb;
                }
            }
            if (half == 1) {
                sm.hpart[s][0][lane] = accL;
                sm.hpart[s][1][lane] = accD;
                sm.hpart[s][2][lane] = accN;
            }
            __syncthreads();
            if (t64 < 32) {
                int k = lane;
                float L = accL + sm.hpart[s][0][k];
                sm.lpv[s][k] = L;
                if (step > 0) {
                    sm.dotv[s][k] = accD + sm.hpart[s][1][k];
                    sm.nb2[s][k]  = accN + sm.hpart[s][2][k];
                }
                float s1 = wredsum(L);
                float s2 = wredsum(L * L);
                if (k == 0) {
                    float lp = sm.lpre[s];
                    sm.Ssum[s]  = s1 + 32.f * lp;
                    sm.SSsum[s] = s2 + 2.f * lp * s1 + 32.f * lp * lp;
                }
            }
        }
        __syncthreads();
        // agent-BN partials (2 quantities)
        if (t < 32) {
            int q = t >> 4, ss = t & 15;
            double v = q ? (double)sm.SSsum[ss] : (double)sm.Ssum[ss];
#pragma unroll
            for (int o = 8; o; o >>= 1) v += __shfl_xor_sync(0xffffffffu, v, o, 16);
            if ((t & 15) == 0) g_part[blockIdx.x][4 + q] = v;
        }
        grid_bar();   // -------- bar 2 (or the only bar at step 0) --------

        // ============== phase C: agent BN + crossover + select ==============
        if (t < 64) {
            int q = t >> 5, ll = t & 31;
            double a = g_part[ll][4 + q] + g_part[ll + 32][4 + q]
                     + g_part[ll + 64][4 + q] + g_part[ll + 96][4 + q];
#pragma unroll
            for (int o = 16; o; o >>= 1) a += __shfl_xor_sync(0xffffffffu, a, o);
            if (ll == 0) sm.bns[4 + q] = a;
        }
        __syncthreads();
        if (t == 0) {
            double mean = sm.bns[4] * (1.0 / 65536.0);
            double var  = sm.bns[5] * (1.0 / 65536.0) - mean * mean;
            sm.bnf[4] = (float)mean;
            sm.bnf[5] = (float)sqrt(var + 1e-5);
        }
        __syncthreads();
        if (t64 < 32) {
            int k = t64;
            float lg = sm.lpv[s][k] + sm.lpre[s];
            float z = (lg - sm.bnf[4]) / sm.bnf[5] * sm.ag + sm.ab;
            float l2 = z;
            if (step > 0) {
                float nbl = sqrtf(sm.nb2[s][k]);
                float div = fmaxf(sm.na[s] * nbl, 1e-8f);
                float d = 1.f + sm.dotv[s][k] / div;
                d = fminf(fmaxf(d, 0.f), 1.f);
                l2 = z * d;
            }
            float mx = l2;
#pragma unroll
            for (int o = 16; o; o >>= 1) mx = fmaxf(mx, __shfl_xor_sync(0xffffffffu, mx, o));
            float e = expf(l2 - mx);
            float se = wredsum(e);
            float y = e / se;
            unsigned long long key =
                ((unsigned long long)__float_as_uint(y) << 32) | (unsigned)(31 - k);
#pragma unroll
            for (int o = 16; o; o >>= 1) {
                unsigned long long kk = __shfl_xor_sync(0xffffffffu, key, o);
                if (kk > key) key = kk;
            }
            if (k == 0) {
                int sl = 31 - (int)(key & 0xFFFFFFFFull);
                sm.sel[s] = sl;
                sm.fcur[s] = sm.pts[s][sl];
            }
        }
        __syncthreads();
        {
            float nc = pv[(s * 32 + sm.sel[s]) * 65 + c];
            sm.cur[s][c] = nc;
            out[((size_t)(b * 64 + c) * 256 + (size_t)j) * 32 + step] = nc;
        }
        __syncthreads();
    }
}

// ----------------- launch -----------------
extern "C" void kernel_launch(void* const* d_in, const int* in_sizes, int n_in,
                              void* d_out, int out_size) {
    const float* x    = (const float*)d_in[0];
    // d_in[1] = xyz (unused by the reference forward)
    const int*   idx  = (const int*)d_in[2];
    const float* attw = (const float*)d_in[3];
    const float* agw  = (const float*)d_in[4];
    const float* agg  = (const float*)d_in[5];
    const float* agb  = (const float*)d_in[6];
    const float* mw   = (const float*)d_in[7];
    const float* mg   = (const float*)d_in[8];
    const float* mb   = (const float*)d_in[9];
    float* out = (float*)d_out;

    cudaFuncSetAttribute(k_topk, cudaFuncAttributeMaxDynamicSharedMemorySize,
                         NPTS * sizeof(unsigned long long));
    cudaFuncSetAttribute(k_walk, cudaFuncAttributeMaxDynamicSharedMemorySize,
                         16 * 32 * 65 * (int)sizeof(float));

    k_prep<<<NB * 128, 256>>>(x, attw);
    k_topk<<<NB, 1024, NPTS * sizeof(unsigned long long)>>>();
    k_walk<<<PBLK, 1024, 16 * 32 * 65 * (int)sizeof(float)>>>(idx, agw, agg, agb, mw, mg, mb, out);
}